// round 12
// baseline (speedup 1.0000x reference)
#include <cuda_runtime.h>
#include <cuda_bf16.h>
#include <cstdint>

#define NN 50000          // nodes
#define NNP 50048         // padded to 128-multiple
#define NE 1600000        // edges
#define TOT (NE + NN)     // edges + self loops
#define KDIM 1028
#define KP 1056           // K padded (33 * 32)
#define DOUT 256
#define NEG 0.2f
#define NBS ((NN + 511) / 512)

#define BK 32
#define KT (KP / BK)              // 33 k-tiles
#define STG 32768                 // bytes per pipeline stage (Ah|Al|Bh|Bl, 8KB each)
#define SMEM_TOT (3 * STG)        // 96 KB, 3-stage pipeline

// ---------------- scratch (static device globals; zero-initialized) ----------------
__device__ float g_xl[(size_t)NNP * DOUT];
__device__ float g_xr[(size_t)NNP * DOUT];
__device__ unsigned short g_ah[(size_t)NNP * KP];   // X hi (bf16 bits), zero-padded
__device__ unsigned short g_al[(size_t)NNP * KP];   // X lo
__device__ unsigned short g_bh[512 * KP];           // W^T hi ([n][k]; n<256: Wl, else Wr)
__device__ unsigned short g_bl[512 * KP];           // W^T lo
__device__ int   g_counts[NN];
__device__ int   g_starts[NN];
__device__ int   g_work[NN];
__device__ int   g_src_sorted[TOT];
__device__ int   g_bsum[NBS];
__device__ int   g_is64;

// ---------------- small helpers ----------------
__device__ __forceinline__ unsigned short bfbits(float f) {
    __nv_bfloat16 h = __float2bfloat16(f);
    return *reinterpret_cast<unsigned short*>(&h);
}
__device__ __forceinline__ float bffloat(unsigned short u) {
    __nv_bfloat16 h = *reinterpret_cast<__nv_bfloat16*>(&u);
    return __bfloat162float(h);
}
__device__ __forceinline__ uint32_t smem_u32(const void* p) {
    uint32_t a;
    asm("{ .reg .u64 t; cvta.to.shared.u64 t, %1; cvt.u32.u64 %0, t; }" : "=r"(a) : "l"(p));
    return a;
}
__device__ __forceinline__ void cpa16(uint32_t s, const void* g) {
    asm volatile("cp.async.cg.shared.global [%0], [%1], 16;" :: "r"(s), "l"(g));
}
__device__ __forceinline__ void ldsm4(uint32_t addr, uint32_t* r) {
    asm volatile("ldmatrix.sync.aligned.m8n8.x4.shared.b16 {%0,%1,%2,%3}, [%4];"
                 : "=r"(r[0]), "=r"(r[1]), "=r"(r[2]), "=r"(r[3]) : "r"(addr));
}
__device__ __forceinline__ void mma16816(float* d, const uint32_t* a, uint32_t b0, uint32_t b1) {
    asm volatile(
        "mma.sync.aligned.m16n8k16.row.col.f32.bf16.bf16.f32 "
        "{%0,%1,%2,%3}, {%4,%5,%6,%7}, {%8,%9}, {%0,%1,%2,%3};"
        : "+f"(d[0]), "+f"(d[1]), "+f"(d[2]), "+f"(d[3])
        : "r"(a[0]), "r"(a[1]), "r"(a[2]), "r"(a[3]), "r"(b0), "r"(b1));
}
// 16B-chunk XOR swizzle: row stride 64B (4 chunks); conflict-free for ldmatrix 8-row reads
__device__ __forceinline__ uint32_t swaddr(uint32_t matbase, int row, int kchunk) {
    return matbase + row * 64 + ((kchunk ^ ((row >> 1) & 3)) * 16);
}

// ---------------- conversions: fp32 -> split bf16 (hi/lo), padded ----------------
__global__ void k_convA(const float* __restrict__ X) {
    size_t idx = (size_t)blockIdx.x * blockDim.x + threadIdx.x;
    const size_t total = (size_t)NN * (KP / 4);
    if (idx >= total) return;
    int row = (int)(idx / (KP / 4));
    int c4  = (int)(idx % (KP / 4)) * 4;
    float4 v = make_float4(0.f, 0.f, 0.f, 0.f);
    if (c4 < KDIM) v = *(const float4*)(X + (size_t)row * KDIM + c4);
    unsigned short h0 = bfbits(v.x), h1 = bfbits(v.y), h2 = bfbits(v.z), h3 = bfbits(v.w);
    unsigned short l0 = bfbits(v.x - bffloat(h0));
    unsigned short l1 = bfbits(v.y - bffloat(h1));
    unsigned short l2 = bfbits(v.z - bffloat(h2));
    unsigned short l3 = bfbits(v.w - bffloat(h3));
    uint2 hv, lv;
    hv.x = (uint32_t)h0 | ((uint32_t)h1 << 16);
    hv.y = (uint32_t)h2 | ((uint32_t)h3 << 16);
    lv.x = (uint32_t)l0 | ((uint32_t)l1 << 16);
    lv.y = (uint32_t)l2 | ((uint32_t)l3 << 16);
    *(uint2*)(g_ah + (size_t)row * KP + c4) = hv;
    *(uint2*)(g_al + (size_t)row * KP + c4) = lv;
}

__global__ void k_convB(const float* __restrict__ Wl, const float* __restrict__ Wr) {
    int idx = blockIdx.x * blockDim.x + threadIdx.x;
    if (idx >= 512 * KP) return;
    int n = idx / KP, k = idx % KP;
    float v = 0.f;
    if (k < KDIM) v = (n < 256) ? Wl[(size_t)k * 256 + n] : Wr[(size_t)k * 256 + (n - 256)];
    unsigned short h = bfbits(v);
    unsigned short l = bfbits(v - bffloat(h));
    g_bh[idx] = h;
    g_bl[idx] = l;
}

// ---------------- edge dtype detection (JAX may downcast int64->int32) ----------------
__global__ void k_detect(const int* __restrict__ e32) {
    if (threadIdx.x == 0 && blockIdx.x == 0) {
        int is64 = 1;
        for (int i = 0; i < 64; i++)
            if (e32[2 * i + 1] != 0) { is64 = 0; break; }
        g_is64 = is64;
    }
}
__device__ __forceinline__ int edge_at(const void* ei, int idx) {
    if (g_is64) return (int)((const long long*)ei)[idx];
    return ((const int*)ei)[idx];
}

// ---------------- CSR build ----------------
__global__ void k_zero_counts() {
    int i = blockIdx.x * blockDim.x + threadIdx.x;
    if (i < NN) g_counts[i] = 0;
}
__global__ void k_hist(const void* __restrict__ ei) {
    int k = blockIdx.x * blockDim.x + threadIdx.x;
    if (k >= TOT) return;
    int dst = (k < NE) ? edge_at(ei, NE + k) : (k - NE);
    if ((unsigned)dst < NN) atomicAdd(&g_counts[dst], 1);
}
__global__ void k_scan1() {
    __shared__ int sh[512];
    int t = threadIdx.x;
    int i = blockIdx.x * 512 + t;
    int v = (i < NN) ? g_counts[i] : 0;
    sh[t] = v;
    __syncthreads();
    #pragma unroll
    for (int o = 1; o < 512; o <<= 1) {
        int u = (t >= o) ? sh[t - o] : 0;
        __syncthreads();
        sh[t] += u;
        __syncthreads();
    }
    if (i < NN) g_starts[i] = sh[t] - v;
    if (t == 511) g_bsum[blockIdx.x] = sh[t];
}
__global__ void k_scan2() {
    if (threadIdx.x == 0 && blockIdx.x == 0) {
        int run = 0;
        for (int b = 0; b < NBS; b++) { int c = g_bsum[b]; g_bsum[b] = run; run += c; }
    }
}
__global__ void k_scan3() {
    int i = blockIdx.x * blockDim.x + threadIdx.x;
    if (i >= NN) return;
    int s = g_starts[i] + g_bsum[i >> 9];
    g_starts[i] = s;
    g_work[i] = s;
}
__global__ void k_scatter(const void* __restrict__ ei) {
    int k = blockIdx.x * blockDim.x + threadIdx.x;
    if (k >= TOT) return;
    int src, dst;
    if (k < NE) { src = edge_at(ei, k); dst = edge_at(ei, NE + k); }
    else        { src = k - NE;         dst = k - NE; }
    if ((unsigned)dst >= NN || (unsigned)src >= NN) return;
    int pos = atomicAdd(&g_work[dst], 1);
    g_src_sorted[pos] = src;
}

// ---------------- split-bf16 HMMA GEMM (mma.sync.m16n8k16) ----------------
// D = Ah@Bh^T + Ah@Bl^T + Al@Bh^T, fp32 accum shared across the 3 passes.
// CTA: BM=128 x BN=128, BK=32, 8 warps, warp tile 64x32.
// grid = (4, NNP/128): bx 0,1 -> g_xl cols [0,128),[128,256); bx 2,3 -> g_xr.
// bx is the FAST grid dim so the 4 column-variants of one row-block are
// schedule-adjacent -> the A hi/lo tile is read from DRAM once and L2-hit 3x.
__device__ __forceinline__ void load_stage(uint32_t sb, int buf, int kt, int m0, int n0, int t) {
    uint32_t base = sb + buf * STG;
    int k0 = kt * BK;
    #pragma unroll
    for (int p = 0; p < 8; p++) {
        int id = p * 256 + t;
        int mat = id >> 9;            // 0 Ah, 1 Al, 2 Bh, 3 Bl (constant per p)
        int cid = id & 511;
        int row = cid >> 2;
        int c = cid & 3;
        uint32_t dst = base + mat * 8192 + (uint32_t)row * 64 + ((c ^ ((row >> 1) & 3)) * 16);
        const unsigned short* src;
        if (mat == 0)      src = g_ah + (size_t)(m0 + row) * KP + k0 + c * 8;
        else if (mat == 1) src = g_al + (size_t)(m0 + row) * KP + k0 + c * 8;
        else if (mat == 2) src = g_bh + (size_t)(n0 + row) * KP + k0 + c * 8;
        else               src = g_bl + (size_t)(n0 + row) * KP + k0 + c * 8;
        cpa16(dst, src);
    }
}

__global__ __launch_bounds__(256, 1) void k_mma() {
    extern __shared__ __align__(128) char smem[];
    uint32_t sb = smem_u32(smem);
    const int t = threadIdx.x;
    const int warp = t >> 5, lane = t & 31;
    const int by = blockIdx.x;                    // column-variant (fast dim)
    const int m0 = blockIdx.y * 128;              // row block
    const int n0 = by * 128;                      // row into 512-row g_bh/g_bl
    float* __restrict__ O = (by < 2) ? g_xl : g_xr;
    const int col0 = (by & 1) * 128;

    const int wm = (warp & 1) * 64;
    const int wn = (warp >> 1) * 32;

    float acc[4][4][4];
    #pragma unroll
    for (int mi = 0; mi < 4; mi++)
        #pragma unroll
        for (int ni = 0; ni < 4; ni++)
            #pragma unroll
            for (int q = 0; q < 4; q++) acc[mi][ni][q] = 0.f;

    // preload stages 0,1
    load_stage(sb, 0, 0, m0, n0, t);
    asm volatile("cp.async.commit_group;" ::: "memory");
    load_stage(sb, 1, 1, m0, n0, t);
    asm volatile("cp.async.commit_group;" ::: "memory");

    for (int kt = 0; kt < KT; kt++) {
        if (kt < KT - 1) asm volatile("cp.async.wait_group 1;" ::: "memory");
        else             asm volatile("cp.async.wait_group 0;" ::: "memory");
        __syncthreads();   // stage kt visible; all warps done with stage kt-1's buffer

        if (kt + 2 < KT) {
            load_stage(sb, (kt + 2) % 3, kt + 2, m0, n0, t);  // overwrites stage kt-1's buffer
            asm volatile("cp.async.commit_group;" ::: "memory");
        }

        uint32_t base = sb + (kt % 3) * STG;
        #pragma unroll
        for (int kk = 0; kk < 2; kk++) {
            uint32_t ah[4][4], al[4][4], bh[2][4], bl[2][4];
            const int kc = kk * 2 + (lane >> 4);
            #pragma unroll
            for (int fi = 0; fi < 4; fi++) {
                int row = wm + fi * 16 + (lane & 15);
                ldsm4(swaddr(base, row, kc), ah[fi]);
                ldsm4(swaddr(base + 8192, row, kc), al[fi]);
            }
            #pragma unroll
            for (int nf = 0; nf < 2; nf++) {
                int row = wn + nf * 16 + (lane & 15);
                ldsm4(swaddr(base + 16384, row, kc), bh[nf]);
                ldsm4(swaddr(base + 24576, row, kc), bl[nf]);
            }
            #pragma unroll
            for (int mi = 0; mi < 4; mi++)
                #pragma unroll
                for (int ni = 0; ni < 4; ni++) {
                    const int nf = ni >> 1, sel = ni & 1;
                    mma16816(acc[mi][ni], ah[mi], bh[nf][sel], bh[nf][sel + 2]);
                    mma16816(acc[mi][ni], ah[mi], bl[nf][sel], bl[nf][sel + 2]);
                    mma16816(acc[mi][ni], al[mi], bh[nf][sel], bh[nf][sel + 2]);
                }
        }
    }

    // epilogue: C frag -> fp32 stores (row m = l/4 (+8), col n = (l%4)*2)
    #pragma unroll
    for (int mi = 0; mi < 4; mi++) {
        int mrow0 = m0 + wm + mi * 16 + (lane >> 2);
        #pragma unroll
        for (int half = 0; half < 2; half++) {
            int m = mrow0 + half * 8;
            if (m < NN) {
                float* op = O + (size_t)m * DOUT + col0 + wn + (lane & 3) * 2;
                #pragma unroll
                for (int ni = 0; ni < 4; ni++) {
                    float2 v = make_float2(acc[mi][ni][half * 2], acc[mi][ni][half * 2 + 1]);
                    *(float2*)(op + ni * 8) = v;
                }
            }
        }
    }
}

// ---------------- fused attention softmax + aggregation ----------------
__global__ __launch_bounds__(256) void k_aggregate(
    const float* __restrict__ att,
    const float* __restrict__ bias,
    float* __restrict__ out)
{
    const int gw = (blockIdx.x * blockDim.x + threadIdx.x) >> 5;
    const int lane = threadIdx.x & 31;
    if (gw >= NN) return;

    const int base = lane * 8;
    float4 xr0 = *(const float4*)(g_xr + (size_t)gw * DOUT + base);
    float4 xr1 = *(const float4*)(g_xr + (size_t)gw * DOUT + base + 4);
    float4 at0 = *(const float4*)(att + base);
    float4 at1 = *(const float4*)(att + base + 4);

    float a0 = 0.f, a1 = 0.f, a2 = 0.f, a3 = 0.f;
    float a4 = 0.f, a5 = 0.f, a6 = 0.f, a7 = 0.f;
    float denom = 0.f;

    const int s = g_starts[gw];
    const int cnt = g_counts[gw];

    for (int b = 0; b < cnt; b += 32) {
        int m = cnt - b; if (m > 32) m = 32;
        int sidx = 0;
        if (b + lane < cnt) sidx = g_src_sorted[s + b + lane];

        int src0 = __shfl_sync(0xffffffffu, sidx, 0);
        const float4* xp = (const float4*)(g_xl + (size_t)src0 * DOUT + base);
        float4 v0 = __ldg(xp);
        float4 v1 = __ldg(xp + 1);

        for (int j = 0; j < m; j++) {
            float4 c0 = v0, c1 = v1;
            if (j + 1 < m) {
                int srcn = __shfl_sync(0xffffffffu, sidx, j + 1);
                const float4* xn = (const float4*)(g_xl + (size_t)srcn * DOUT + base);
                v0 = __ldg(xn);
                v1 = __ldg(xn + 1);
            }

            float e = 0.f, z, l;
            z = c0.x + xr0.x; l = fmaxf(z, NEG * z); e = fmaf(l, at0.x, e);
            z = c0.y + xr0.y; l = fmaxf(z, NEG * z); e = fmaf(l, at0.y, e);
            z = c0.z + xr0.z; l = fmaxf(z, NEG * z); e = fmaf(l, at0.z, e);
            z = c0.w + xr0.w; l = fmaxf(z, NEG * z); e = fmaf(l, at0.w, e);
            z = c1.x + xr1.x; l = fmaxf(z, NEG * z); e = fmaf(l, at1.x, e);
            z = c1.y + xr1.y; l = fmaxf(z, NEG * z); e = fmaf(l, at1.y, e);
            z = c1.z + xr1.z; l = fmaxf(z, NEG * z); e = fmaf(l, at1.z, e);
            z = c1.w + xr1.w; l = fmaxf(z, NEG * z); e = fmaf(l, at1.w, e);

            e += __shfl_xor_sync(0xffffffffu, e, 16);
            e += __shfl_xor_sync(0xffffffffu, e, 8);
            e += __shfl_xor_sync(0xffffffffu, e, 4);
            e += __shfl_xor_sync(0xffffffffu, e, 2);
            e += __shfl_xor_sync(0xffffffffu, e, 1);

            float p = __expf(e);
            denom += p;
            a0 = fmaf(p, c0.x, a0); a1 = fmaf(p, c0.y, a1);
            a2 = fmaf(p, c0.z, a2); a3 = fmaf(p, c0.w, a3);
            a4 = fmaf(p, c1.x, a4); a5 = fmaf(p, c1.y, a5);
            a6 = fmaf(p, c1.z, a6); a7 = fmaf(p, c1.w, a7);
        }
    }

    float r = 1.0f / denom;
    float4 b0 = *(const float4*)(bias + base);
    float4 b1 = *(const float4*)(bias + base + 4);
    float4 o0, o1;
    o0.x = fmaf(a0, r, b0.x); o0.y = fmaf(a1, r, b0.y);
    o0.z = fmaf(a2, r, b0.z); o0.w = fmaf(a3, r, b0.w);
    o1.x = fmaf(a4, r, b1.x); o1.y = fmaf(a5, r, b1.y);
    o1.z = fmaf(a6, r, b1.z); o1.w = fmaf(a7, r, b1.w);
    float* op = out + (size_t)gw * DOUT + base;
    *(float4*)(op)     = o0;
    *(float4*)(op + 4) = o1;
}

// ---------------- launch ----------------
extern "C" void kernel_launch(void* const* d_in, const int* in_sizes, int n_in,
                              void* d_out, int out_size) {
    const float* x    = (const float*)d_in[0];
    const void*  ei   = d_in[1];
    const float* Wl   = (const float*)d_in[2];
    const float* Wr   = (const float*)d_in[3];
    const float* att  = (const float*)d_in[4];
    const float* bias = (const float*)d_in[5];
    float*       out  = (float*)d_out;

    cudaFuncSetAttribute(k_mma, cudaFuncAttributeMaxDynamicSharedMemorySize, SMEM_TOT);

    // 1-5: conversions + CSR front half (k_mma is launch #6 -> profiled by -s 5 -c 1)
    {
        size_t tot = (size_t)NN * (KP / 4);
        k_convA<<<(unsigned)((tot + 255) / 256), 256>>>(x);
    }
    k_convB<<<(512 * KP + 255) / 256, 256>>>(Wl, Wr);
    k_detect<<<1, 32>>>((const int*)ei);
    k_zero_counts<<<(NN + 255) / 256, 256>>>();
    k_hist<<<(TOT + 255) / 256, 256>>>(ei);

    // 6: split-bf16 HMMA GEMM (xl / xr); column-variant fast grid dim for L2 A-reuse
    k_mma<<<dim3(4, NNP / 128), 256, SMEM_TOT>>>();

    // CSR back half
    k_scan1<<<NBS, 512>>>();
    k_scan2<<<1, 32>>>();
    k_scan3<<<(NN + 255) / 256, 256>>>();
    k_scatter<<<(TOT + 255) / 256, 256>>>(ei);

    // fused softmax + aggregation
    k_aggregate<<<(NN * 32) / 256, 256>>>(att, bias, out);
}

// round 13
// speedup vs baseline: 1.2949x; 1.2949x over previous
#include <cuda_runtime.h>
#include <cuda_bf16.h>
#include <cstdint>

#define NN 50000          // nodes
#define NNP 50048         // padded to 128-multiple
#define NE 1600000        // edges
#define TOT (NE + NN)     // edges + self loops
#define KDIM 1028
#define KP 1056           // K padded (33 * 32)
#define DOUT 256
#define NEG 0.2f
#define NBS ((NN + 511) / 512)

#define BK 32
#define KT (KP / BK)              // 33 k-tiles
// smem layout (per CTA, 128 KB):
//   B stages:   3 x 16 KB  (Bh 8K + Bl 8K, swizzled)      @ 0
//   rawA:       3 x 16 KB  (128 rows x 32 fp32, linear)    @ 48K
//   convA:      2 x 16 KB  (Ah 8K + Al 8K, swizzled)       @ 96K
#define B_OFF(buf)   ((buf) * 16384)
#define RAW_OFF(buf) (49152 + (buf) * 16384)
#define CA_OFF(buf)  (98304 + (buf) * 16384)
#define SMEM_TOT 131072

// ---------------- scratch (static device globals; no allocation) ----------------
__device__ float g_xl[(size_t)NNP * DOUT];
__device__ float g_xr[(size_t)NNP * DOUT];
__device__ unsigned short g_bh[512 * KP];   // W^T hi ([n][k]; n<256: Wl, else Wr)
__device__ unsigned short g_bl[512 * KP];   // W^T lo
__device__ int   g_counts[NN];
__device__ int   g_starts[NN];
__device__ int   g_work[NN];
__device__ int   g_src_sorted[TOT];
__device__ int   g_bsum[NBS];
__device__ int   g_is64;

// ---------------- small helpers ----------------
__device__ __forceinline__ unsigned short bfbits(float f) {
    __nv_bfloat16 h = __float2bfloat16(f);
    return *reinterpret_cast<unsigned short*>(&h);
}
__device__ __forceinline__ float bffloat(unsigned short u) {
    __nv_bfloat16 h = *reinterpret_cast<__nv_bfloat16*>(&u);
    return __bfloat162float(h);
}
__device__ __forceinline__ uint32_t smem_u32(const void* p) {
    uint32_t a;
    asm("{ .reg .u64 t; cvta.to.shared.u64 t, %1; cvt.u32.u64 %0, t; }" : "=r"(a) : "l"(p));
    return a;
}
__device__ __forceinline__ void cpa16(uint32_t s, const void* g) {
    asm volatile("cp.async.cg.shared.global [%0], [%1], 16;" :: "r"(s), "l"(g));
}
__device__ __forceinline__ void ldsm4(uint32_t addr, uint32_t* r) {
    asm volatile("ldmatrix.sync.aligned.m8n8.x4.shared.b16 {%0,%1,%2,%3}, [%4];"
                 : "=r"(r[0]), "=r"(r[1]), "=r"(r[2]), "=r"(r[3]) : "r"(addr));
}
__device__ __forceinline__ void mma16816(float* d, const uint32_t* a, uint32_t b0, uint32_t b1) {
    asm volatile(
        "mma.sync.aligned.m16n8k16.row.col.f32.bf16.bf16.f32 "
        "{%0,%1,%2,%3}, {%4,%5,%6,%7}, {%8,%9}, {%0,%1,%2,%3};"
        : "+f"(d[0]), "+f"(d[1]), "+f"(d[2]), "+f"(d[3])
        : "r"(a[0]), "r"(a[1]), "r"(a[2]), "r"(a[3]), "r"(b0), "r"(b1));
}
// 16B-chunk XOR swizzle inside a 128x32 bf16 tile: row stride 64B, 4 chunks/row
__device__ __forceinline__ uint32_t swoff(int row, int kchunk) {
    return (uint32_t)row * 64 + ((kchunk ^ ((row >> 1) & 3)) * 16);
}

// ---------------- convB: fp32 W -> split bf16 W^T (hi/lo), padded ----------------
__global__ void k_convB(const float* __restrict__ Wl, const float* __restrict__ Wr) {
    int idx = blockIdx.x * blockDim.x + threadIdx.x;
    if (idx >= 512 * KP) return;
    int n = idx / KP, k = idx % KP;
    float v = 0.f;
    if (k < KDIM) v = (n < 256) ? Wl[(size_t)k * 256 + n] : Wr[(size_t)k * 256 + (n - 256)];
    unsigned short h = bfbits(v);
    unsigned short l = bfbits(v - bffloat(h));
    g_bh[idx] = h;
    g_bl[idx] = l;
}

// ---------------- edge dtype detection (JAX may downcast int64->int32) ----------------
__global__ void k_detect(const int* __restrict__ e32) {
    if (threadIdx.x == 0 && blockIdx.x == 0) {
        int is64 = 1;
        for (int i = 0; i < 64; i++)
            if (e32[2 * i + 1] != 0) { is64 = 0; break; }
        g_is64 = is64;
    }
}
__device__ __forceinline__ int edge_at(const void* ei, int idx) {
    if (g_is64) return (int)((const long long*)ei)[idx];
    return ((const int*)ei)[idx];
}

// ---------------- CSR build ----------------
__global__ void k_zero_counts() {
    int i = blockIdx.x * blockDim.x + threadIdx.x;
    if (i < NN) g_counts[i] = 0;
}
__global__ void k_hist(const void* __restrict__ ei) {
    int k = blockIdx.x * blockDim.x + threadIdx.x;
    if (k >= TOT) return;
    int dst = (k < NE) ? edge_at(ei, NE + k) : (k - NE);
    if ((unsigned)dst < NN) atomicAdd(&g_counts[dst], 1);
}
__global__ void k_scan1() {
    __shared__ int sh[512];
    int t = threadIdx.x;
    int i = blockIdx.x * 512 + t;
    int v = (i < NN) ? g_counts[i] : 0;
    sh[t] = v;
    __syncthreads();
    #pragma unroll
    for (int o = 1; o < 512; o <<= 1) {
        int u = (t >= o) ? sh[t - o] : 0;
        __syncthreads();
        sh[t] += u;
        __syncthreads();
    }
    if (i < NN) g_starts[i] = sh[t] - v;
    if (t == 511) g_bsum[blockIdx.x] = sh[t];
}
__global__ void k_scan2() {
    if (threadIdx.x == 0 && blockIdx.x == 0) {
        int run = 0;
        for (int b = 0; b < NBS; b++) { int c = g_bsum[b]; g_bsum[b] = run; run += c; }
    }
}
__global__ void k_scan3() {
    int i = blockIdx.x * blockDim.x + threadIdx.x;
    if (i >= NN) return;
    int s = g_starts[i] + g_bsum[i >> 9];
    g_starts[i] = s;
    g_work[i] = s;
}
__global__ void k_scatter(const void* __restrict__ ei) {
    int k = blockIdx.x * blockDim.x + threadIdx.x;
    if (k >= TOT) return;
    int src, dst;
    if (k < NE) { src = edge_at(ei, k); dst = edge_at(ei, NE + k); }
    else        { src = k - NE;         dst = k - NE; }
    if ((unsigned)dst >= NN || (unsigned)src >= NN) return;
    int pos = atomicAdd(&g_work[dst], 1);
    g_src_sorted[pos] = src;
}

// ---------------- fused conv + split-bf16 HMMA GEMM ----------------
// D = Ah@Bh^T + Ah@Bl^T + Al@Bh^T, fp32 accum shared across the 3 passes.
// A is loaded as RAW fp32 X and split to bf16 hi/lo inside the kernel.
// CTA: BM=128 x BN=128, BK=32, 8 warps, warp tile 64x32.
// grid = (4, NNP/128): bx fast so the 4 column-variants of one row-block are
// schedule-adjacent -> X tile read from DRAM once, L2-hit 3x.
__device__ __forceinline__ void load_B_stage(uint32_t sb, int buf, int kt, int n0, int t) {
    int k0 = kt * BK;
    #pragma unroll
    for (int p = 0; p < 4; p++) {
        int id = p * 256 + t;
        int mat = id >> 9;            // 0 Bh, 1 Bl
        int cid = id & 511;
        int row = cid >> 2;
        int c = cid & 3;
        uint32_t dst = sb + B_OFF(buf) + mat * 8192 + swoff(row, c);
        const unsigned short* src = (mat ? g_bl : g_bh) + (size_t)(n0 + row) * KP + k0 + c * 8;
        cpa16(dst, src);
    }
}

__device__ __forceinline__ void load_rawA_stage(uint32_t sb, char* smem, int buf, int kt,
                                                int m0, int t, const float* __restrict__ X) {
    int k0 = kt * BK;
    #pragma unroll
    for (int p = 0; p < 4; p++) {
        int id = p * 256 + t;
        int row = id >> 3;            // 0..127
        int c = id & 7;               // 8 chunks of 4 floats per row
        int col = k0 + c * 4;
        uint32_t dsto = RAW_OFF(buf) + (uint32_t)row * 128 + c * 16;
        int m = m0 + row;
        if (m < NN && col + 4 <= KDIM) {
            cpa16(sb + dsto, X + (size_t)m * KDIM + col);
        } else {
            *(float4*)(smem + dsto) = make_float4(0.f, 0.f, 0.f, 0.f);
        }
    }
}

// split raw fp32 stage -> swizzled bf16 hi/lo stage
__device__ __forceinline__ void convert_stage(char* smem, int rawbuf, int cbuf, int t) {
    const int row = t >> 1;
    const int half = t & 1;            // cols [half*16, half*16+16)
    const float4* rp = (const float4*)(smem + RAW_OFF(rawbuf) + (uint32_t)row * 128 + half * 64);
    float f[16];
    #pragma unroll
    for (int q = 0; q < 4; q++) {
        float4 v = rp[q];
        f[q * 4 + 0] = v.x; f[q * 4 + 1] = v.y; f[q * 4 + 2] = v.z; f[q * 4 + 3] = v.w;
    }
    uint32_t hw[8], lw[8];
    #pragma unroll
    for (int j = 0; j < 8; j++) {
        unsigned short h0 = bfbits(f[2 * j]);
        unsigned short h1 = bfbits(f[2 * j + 1]);
        unsigned short l0 = bfbits(f[2 * j] - bffloat(h0));
        unsigned short l1 = bfbits(f[2 * j + 1] - bffloat(h1));
        hw[j] = (uint32_t)h0 | ((uint32_t)h1 << 16);
        lw[j] = (uint32_t)l0 | ((uint32_t)l1 << 16);
    }
    #pragma unroll
    for (int cc = 0; cc < 2; cc++) {
        int c = half * 2 + cc;
        uint32_t off = swoff(row, c);
        *(uint4*)(smem + CA_OFF(cbuf) + off) =
            make_uint4(hw[cc * 4], hw[cc * 4 + 1], hw[cc * 4 + 2], hw[cc * 4 + 3]);
        *(uint4*)(smem + CA_OFF(cbuf) + 8192 + off) =
            make_uint4(lw[cc * 4], lw[cc * 4 + 1], lw[cc * 4 + 2], lw[cc * 4 + 3]);
    }
}

__global__ __launch_bounds__(256, 1) void k_mma(const float* __restrict__ X) {
    extern __shared__ __align__(128) char smem[];
    uint32_t sb = smem_u32(smem);
    const int t = threadIdx.x;
    const int warp = t >> 5, lane = t & 31;
    const int by = blockIdx.x;                    // column-variant (fast dim)
    const int m0 = blockIdx.y * 128;              // row block
    const int n0 = by * 128;                      // row into 512-row g_bh/g_bl
    float* __restrict__ O = (by < 2) ? g_xl : g_xr;
    const int col0 = (by & 1) * 128;

    const int wm = (warp & 1) * 64;
    const int wn = (warp >> 1) * 32;

    float acc[4][4][4];
    #pragma unroll
    for (int mi = 0; mi < 4; mi++)
        #pragma unroll
        for (int ni = 0; ni < 4; ni++)
            #pragma unroll
            for (int q = 0; q < 4; q++) acc[mi][ni][q] = 0.f;

    // prologue: stages 0,1 in flight; convert stage 0
    load_rawA_stage(sb, smem, 0, 0, m0, t, X);
    load_B_stage(sb, 0, 0, n0, t);
    asm volatile("cp.async.commit_group;" ::: "memory");
    load_rawA_stage(sb, smem, 1, 1, m0, t, X);
    load_B_stage(sb, 1, 1, n0, t);
    asm volatile("cp.async.commit_group;" ::: "memory");
    asm volatile("cp.async.wait_group 1;" ::: "memory");
    __syncthreads();
    convert_stage(smem, 0, 0, t);
    __syncthreads();

    for (int kt = 0; kt < KT; kt++) {
        // issue stage kt+2 (raw A + B)
        if (kt + 2 < KT) {
            load_rawA_stage(sb, smem, (kt + 2) % 3, kt + 2, m0, t, X);
            load_B_stage(sb, (kt + 2) % 3, kt + 2, n0, t);
            asm volatile("cp.async.commit_group;" ::: "memory");
        }

        // MMA over conv[kt&1] (A) and B[kt%3]
        uint32_t abase = sb + CA_OFF(kt & 1);
        uint32_t bbase = sb + B_OFF(kt % 3);
        #pragma unroll
        for (int kk = 0; kk < 2; kk++) {
            uint32_t ah[4][4], al[4][4], bh[2][4], bl[2][4];
            const int kc = kk * 2 + (lane >> 4);
            #pragma unroll
            for (int fi = 0; fi < 4; fi++) {
                int row = wm + fi * 16 + (lane & 15);
                ldsm4(abase + swoff(row, kc), ah[fi]);
                ldsm4(abase + 8192 + swoff(row, kc), al[fi]);
            }
            #pragma unroll
            for (int nf = 0; nf < 2; nf++) {
                int row = wn + nf * 16 + (lane & 15);
                ldsm4(bbase + swoff(row, kc), bh[nf]);
                ldsm4(bbase + 8192 + swoff(row, kc), bl[nf]);
            }
            #pragma unroll
            for (int mi = 0; mi < 4; mi++)
                #pragma unroll
                for (int ni = 0; ni < 4; ni++) {
                    const int nf = ni >> 1, sel = ni & 1;
                    mma16816(acc[mi][ni], ah[mi], bh[nf][sel], bh[nf][sel + 2]);
                    mma16816(acc[mi][ni], ah[mi], bl[nf][sel], bl[nf][sel + 2]);
                    mma16816(acc[mi][ni], al[mi], bh[nf][sel], bh[nf][sel + 2]);
                }
        }

        // prepare stage kt+1: wait its cp.async, then convert raw -> conv[(kt+1)&1]
        if (kt + 1 < KT) {
            if (kt + 2 < KT) asm volatile("cp.async.wait_group 1;" ::: "memory");
            else             asm volatile("cp.async.wait_group 0;" ::: "memory");
            __syncthreads();   // all warps done with MMA kt; raw kt+1 + B kt+1 visible
            convert_stage(smem, (kt + 1) % 3, (kt + 1) & 1, t);
            __syncthreads();   // converted A visible to all warps
        }
    }

    // epilogue: C frag -> fp32 stores (row m = l/4 (+8), col n = (l%4)*2)
    #pragma unroll
    for (int mi = 0; mi < 4; mi++) {
        int mrow0 = m0 + wm + mi * 16 + (lane >> 2);
        #pragma unroll
        for (int half = 0; half < 2; half++) {
            int m = mrow0 + half * 8;
            if (m < NN) {
                float* op = O + (size_t)m * DOUT + col0 + wn + (lane & 3) * 2;
                #pragma unroll
                for (int ni = 0; ni < 4; ni++) {
                    float2 v = make_float2(acc[mi][ni][half * 2], acc[mi][ni][half * 2 + 1]);
                    *(float2*)(op + ni * 8) = v;
                }
            }
        }
    }
}

// ---------------- fused attention softmax + aggregation ----------------
__global__ __launch_bounds__(256) void k_aggregate(
    const float* __restrict__ att,
    const float* __restrict__ bias,
    float* __restrict__ out)
{
    const int gw = (blockIdx.x * blockDim.x + threadIdx.x) >> 5;
    const int lane = threadIdx.x & 31;
    if (gw >= NN) return;

    const int base = lane * 8;
    float4 xr0 = *(const float4*)(g_xr + (size_t)gw * DOUT + base);
    float4 xr1 = *(const float4*)(g_xr + (size_t)gw * DOUT + base + 4);
    float4 at0 = *(const float4*)(att + base);
    float4 at1 = *(const float4*)(att + base + 4);

    float a0 = 0.f, a1 = 0.f, a2 = 0.f, a3 = 0.f;
    float a4 = 0.f, a5 = 0.f, a6 = 0.f, a7 = 0.f;
    float denom = 0.f;

    const int s = g_starts[gw];
    const int cnt = g_counts[gw];

    for (int b = 0; b < cnt; b += 32) {
        int m = cnt - b; if (m > 32) m = 32;
        int sidx = 0;
        if (b + lane < cnt) sidx = g_src_sorted[s + b + lane];

        int src0 = __shfl_sync(0xffffffffu, sidx, 0);
        const float4* xp = (const float4*)(g_xl + (size_t)src0 * DOUT + base);
        float4 v0 = __ldg(xp);
        float4 v1 = __ldg(xp + 1);

        for (int j = 0; j < m; j++) {
            float4 c0 = v0, c1 = v1;
            if (j + 1 < m) {
                int srcn = __shfl_sync(0xffffffffu, sidx, j + 1);
                const float4* xn = (const float4*)(g_xl + (size_t)srcn * DOUT + base);
                v0 = __ldg(xn);
                v1 = __ldg(xn + 1);
            }

            float e = 0.f, z, l;
            z = c0.x + xr0.x; l = fmaxf(z, NEG * z); e = fmaf(l, at0.x, e);
            z = c0.y + xr0.y; l = fmaxf(z, NEG * z); e = fmaf(l, at0.y, e);
            z = c0.z + xr0.z; l = fmaxf(z, NEG * z); e = fmaf(l, at0.z, e);
            z = c0.w + xr0.w; l = fmaxf(z, NEG * z); e = fmaf(l, at0.w, e);
            z = c1.x + xr1.x; l = fmaxf(z, NEG * z); e = fmaf(l, at1.x, e);
            z = c1.y + xr1.y; l = fmaxf(z, NEG * z); e = fmaf(l, at1.y, e);
            z = c1.z + xr1.z; l = fmaxf(z, NEG * z); e = fmaf(l, at1.z, e);
            z = c1.w + xr1.w; l = fmaxf(z, NEG * z); e = fmaf(l, at1.w, e);

            e += __shfl_xor_sync(0xffffffffu, e, 16);
            e += __shfl_xor_sync(0xffffffffu, e, 8);
            e += __shfl_xor_sync(0xffffffffu, e, 4);
            e += __shfl_xor_sync(0xffffffffu, e, 2);
            e += __shfl_xor_sync(0xffffffffu, e, 1);

            float p = __expf(e);
            denom += p;
            a0 = fmaf(p, c0.x, a0); a1 = fmaf(p, c0.y, a1);
            a2 = fmaf(p, c0.z, a2); a3 = fmaf(p, c0.w, a3);
            a4 = fmaf(p, c1.x, a4); a5 = fmaf(p, c1.y, a5);
            a6 = fmaf(p, c1.z, a6); a7 = fmaf(p, c1.w, a7);
        }
    }

    float r = 1.0f / denom;
    float4 b0 = *(const float4*)(bias + base);
    float4 b1 = *(const float4*)(bias + base + 4);
    float4 o0, o1;
    o0.x = fmaf(a0, r, b0.x); o0.y = fmaf(a1, r, b0.y);
    o0.z = fmaf(a2, r, b0.z); o0.w = fmaf(a3, r, b0.w);
    o1.x = fmaf(a4, r, b1.x); o1.y = fmaf(a5, r, b1.y);
    o1.z = fmaf(a6, r, b1.z); o1.w = fmaf(a7, r, b1.w);
    float* op = out + (size_t)gw * DOUT + base;
    *(float4*)(op)     = o0;
    *(float4*)(op + 4) = o1;
}

// ---------------- launch ----------------
extern "C" void kernel_launch(void* const* d_in, const int* in_sizes, int n_in,
                              void* d_out, int out_size) {
    const float* x    = (const float*)d_in[0];
    const void*  ei   = d_in[1];
    const float* Wl   = (const float*)d_in[2];
    const float* Wr   = (const float*)d_in[3];
    const float* att  = (const float*)d_in[4];
    const float* bias = (const float*)d_in[5];
    float*       out  = (float*)d_out;

    cudaFuncSetAttribute(k_mma, cudaFuncAttributeMaxDynamicSharedMemorySize, SMEM_TOT);

    // launch order tuned so k_mma is my 4th launch (ncu -s 5 -c 1 with ~2
    // harness-prepended launches -> k_mma is the profiled one)
    k_convB<<<(512 * KP + 255) / 256, 256>>>(Wl, Wr);      // 1
    k_detect<<<1, 32>>>((const int*)ei);                   // 2
    k_zero_counts<<<(NN + 255) / 256, 256>>>();            // 3

    // 4: fused conv + split-bf16 HMMA GEMM (xl / xr)
    k_mma<<<dim3(4, NNP / 128), 256, SMEM_TOT>>>(x);

    // CSR build (independent of GEMM)
    k_hist<<<(TOT + 255) / 256, 256>>>(ei);                // 5
    k_scan1<<<NBS, 512>>>();                               // 6
    k_scan2<<<1, 32>>>();                                  // 7
    k_scan3<<<(NN + 255) / 256, 256>>>();                  // 8
    k_scatter<<<(TOT + 255) / 256, 256>>>(ei);             // 9

    // fused softmax + aggregation
    k_aggregate<<<(NN * 32) / 256, 256>>>(att, bias, out); // 10
}

// round 14
// speedup vs baseline: 1.5190x; 1.1730x over previous
#include <cuda_runtime.h>
#include <cuda_bf16.h>
#include <cstdint>

#define NN 50000          // nodes
#define NNP 50048         // padded to 128-multiple
#define NE 1600000        // edges
#define TOT (NE + NN)     // edges + self loops
#define KDIM 1028
#define KP 1056           // K padded (33 * 32)
#define DOUT 256
#define NEG 0.2f
#define NBS ((NN + 511) / 512)

#define BK 32
#define KT (KP / BK)              // 33 k-tiles
// smem layout (per CTA, 112 KB -> 2 CTAs/SM on 228KB):
//   B stages:   3 x 16 KB  (Bh 8K + Bl 8K, swizzled)      @ 0
//   rawA:       2 x 16 KB  (128 rows x 32 fp32, linear)    @ 48K
//   convA:      2 x 16 KB  (Ah 8K + Al 8K, swizzled)       @ 80K
#define B_OFF(buf)   ((buf) * 16384)
#define RAW_OFF(buf) (49152 + (buf) * 16384)
#define CA_OFF(buf)  (81920 + (buf) * 16384)
#define SMEM_TOT 114688

// ---------------- scratch (static device globals; no allocation) ----------------
__device__ float g_xl[(size_t)NNP * DOUT];
__device__ float g_xr[(size_t)NNP * DOUT];
__device__ unsigned short g_bh[512 * KP];   // W^T hi ([n][k]; n<256: Wl, else Wr)
__device__ unsigned short g_bl[512 * KP];   // W^T lo
__device__ int   g_counts[NN];
__device__ int   g_starts[NN];
__device__ int   g_work[NN];
__device__ int   g_src_sorted[TOT];
__device__ int   g_bsum[NBS];
__device__ int   g_is64;

// ---------------- small helpers ----------------
__device__ __forceinline__ unsigned short bfbits(float f) {
    __nv_bfloat16 h = __float2bfloat16(f);
    return *reinterpret_cast<unsigned short*>(&h);
}
__device__ __forceinline__ float bffloat(unsigned short u) {
    __nv_bfloat16 h = *reinterpret_cast<__nv_bfloat16*>(&u);
    return __bfloat162float(h);
}
__device__ __forceinline__ uint32_t smem_u32(const void* p) {
    uint32_t a;
    asm("{ .reg .u64 t; cvta.to.shared.u64 t, %1; cvt.u32.u64 %0, t; }" : "=r"(a) : "l"(p));
    return a;
}
__device__ __forceinline__ void cpa16(uint32_t s, const void* g) {
    asm volatile("cp.async.cg.shared.global [%0], [%1], 16;" :: "r"(s), "l"(g));
}
__device__ __forceinline__ void ldsm4(uint32_t addr, uint32_t* r) {
    asm volatile("ldmatrix.sync.aligned.m8n8.x4.shared.b16 {%0,%1,%2,%3}, [%4];"
                 : "=r"(r[0]), "=r"(r[1]), "=r"(r[2]), "=r"(r[3]) : "r"(addr));
}
__device__ __forceinline__ void mma16816(float* d, const uint32_t* a, uint32_t b0, uint32_t b1) {
    asm volatile(
        "mma.sync.aligned.m16n8k16.row.col.f32.bf16.bf16.f32 "
        "{%0,%1,%2,%3}, {%4,%5,%6,%7}, {%8,%9}, {%0,%1,%2,%3};"
        : "+f"(d[0]), "+f"(d[1]), "+f"(d[2]), "+f"(d[3])
        : "r"(a[0]), "r"(a[1]), "r"(a[2]), "r"(a[3]), "r"(b0), "r"(b1));
}
// 16B-chunk XOR swizzle inside a 128x32 bf16 tile: row stride 64B, 4 chunks/row
__device__ __forceinline__ uint32_t swoff(int row, int kchunk) {
    return (uint32_t)row * 64 + ((kchunk ^ ((row >> 1) & 3)) * 16);
}

// ---------------- convB: fp32 W -> split bf16 W^T (hi/lo), padded ----------------
__global__ void k_convB(const float* __restrict__ Wl, const float* __restrict__ Wr) {
    int idx = blockIdx.x * blockDim.x + threadIdx.x;
    if (idx >= 512 * KP) return;
    int n = idx / KP, k = idx % KP;
    float v = 0.f;
    if (k < KDIM) v = (n < 256) ? Wl[(size_t)k * 256 + n] : Wr[(size_t)k * 256 + (n - 256)];
    unsigned short h = bfbits(v);
    unsigned short l = bfbits(v - bffloat(h));
    g_bh[idx] = h;
    g_bl[idx] = l;
}

// ---------------- edge dtype detection (JAX may downcast int64->int32) ----------------
__global__ void k_detect(const int* __restrict__ e32) {
    if (threadIdx.x == 0 && blockIdx.x == 0) {
        int is64 = 1;
        for (int i = 0; i < 64; i++)
            if (e32[2 * i + 1] != 0) { is64 = 0; break; }
        g_is64 = is64;
    }
}
__device__ __forceinline__ int edge_at(const void* ei, int idx) {
    if (g_is64) return (int)((const long long*)ei)[idx];
    return ((const int*)ei)[idx];
}

// ---------------- CSR build ----------------
__global__ void k_zero_counts() {
    int i = blockIdx.x * blockDim.x + threadIdx.x;
    if (i < NN) g_counts[i] = 0;
}
__global__ void k_hist(const void* __restrict__ ei) {
    int k = blockIdx.x * blockDim.x + threadIdx.x;
    if (k >= TOT) return;
    int dst = (k < NE) ? edge_at(ei, NE + k) : (k - NE);
    if ((unsigned)dst < NN) atomicAdd(&g_counts[dst], 1);
}
__global__ void k_scan1() {
    __shared__ int sh[512];
    int t = threadIdx.x;
    int i = blockIdx.x * 512 + t;
    int v = (i < NN) ? g_counts[i] : 0;
    sh[t] = v;
    __syncthreads();
    #pragma unroll
    for (int o = 1; o < 512; o <<= 1) {
        int u = (t >= o) ? sh[t - o] : 0;
        __syncthreads();
        sh[t] += u;
        __syncthreads();
    }
    if (i < NN) g_starts[i] = sh[t] - v;
    if (t == 511) g_bsum[blockIdx.x] = sh[t];
}
__global__ void k_scan2() {
    if (threadIdx.x == 0 && blockIdx.x == 0) {
        int run = 0;
        for (int b = 0; b < NBS; b++) { int c = g_bsum[b]; g_bsum[b] = run; run += c; }
    }
}
__global__ void k_scan3() {
    int i = blockIdx.x * blockDim.x + threadIdx.x;
    if (i >= NN) return;
    int s = g_starts[i] + g_bsum[i >> 9];
    g_starts[i] = s;
    g_work[i] = s;
}
__global__ void k_scatter(const void* __restrict__ ei) {
    int k = blockIdx.x * blockDim.x + threadIdx.x;
    if (k >= TOT) return;
    int src, dst;
    if (k < NE) { src = edge_at(ei, k); dst = edge_at(ei, NE + k); }
    else        { src = k - NE;         dst = k - NE; }
    if ((unsigned)dst >= NN || (unsigned)src >= NN) return;
    int pos = atomicAdd(&g_work[dst], 1);
    g_src_sorted[pos] = src;
}

// ---------------- fused conv + split-bf16 HMMA GEMM ----------------
// D = Ah@Bh^T + Ah@Bl^T + Al@Bh^T, fp32 accum shared across the 3 passes.
// A loaded as RAW fp32 X, split to bf16 hi/lo in-kernel (2-stage raw ring:
// raw[k%2] is freed by the conversion at the end of iter k-1, sync-fenced).
// CTA: BM=128 x BN=128, BK=32, 8 warps, warp tile 64x32, 2 CTAs/SM.
// grid = (4, NNP/128): bx fast -> X tile L2-reused across the 4 col-variants.
__device__ __forceinline__ void load_B_stage(uint32_t sb, int buf, int kt, int n0, int t) {
    int k0 = kt * BK;
    #pragma unroll
    for (int p = 0; p < 4; p++) {
        int id = p * 256 + t;
        int mat = id >> 9;            // 0 Bh, 1 Bl
        int cid = id & 511;
        int row = cid >> 2;
        int c = cid & 3;
        uint32_t dst = sb + B_OFF(buf) + mat * 8192 + swoff(row, c);
        const unsigned short* src = (mat ? g_bl : g_bh) + (size_t)(n0 + row) * KP + k0 + c * 8;
        cpa16(dst, src);
    }
}

__device__ __forceinline__ void load_rawA_stage(uint32_t sb, char* smem, int buf, int kt,
                                                int m0, int t, const float* __restrict__ X) {
    int k0 = kt * BK;
    #pragma unroll
    for (int p = 0; p < 4; p++) {
        int id = p * 256 + t;
        int row = id >> 3;            // 0..127
        int c = id & 7;               // 8 chunks of 4 floats per row
        int col = k0 + c * 4;
        uint32_t dsto = RAW_OFF(buf) + (uint32_t)row * 128 + c * 16;
        int m = m0 + row;
        if (m < NN && col + 4 <= KDIM) {
            cpa16(sb + dsto, X + (size_t)m * KDIM + col);
        } else {
            *(float4*)(smem + dsto) = make_float4(0.f, 0.f, 0.f, 0.f);
        }
    }
}

// split raw fp32 stage -> swizzled bf16 hi/lo stage
__device__ __forceinline__ void convert_stage(char* smem, int rawbuf, int cbuf, int t) {
    const int row = t >> 1;
    const int half = t & 1;            // cols [half*16, half*16+16)
    const float4* rp = (const float4*)(smem + RAW_OFF(rawbuf) + (uint32_t)row * 128 + half * 64);
    float f[16];
    #pragma unroll
    for (int q = 0; q < 4; q++) {
        float4 v = rp[q];
        f[q * 4 + 0] = v.x; f[q * 4 + 1] = v.y; f[q * 4 + 2] = v.z; f[q * 4 + 3] = v.w;
    }
    uint32_t hw[8], lw[8];
    #pragma unroll
    for (int j = 0; j < 8; j++) {
        unsigned short h0 = bfbits(f[2 * j]);
        unsigned short h1 = bfbits(f[2 * j + 1]);
        unsigned short l0 = bfbits(f[2 * j] - bffloat(h0));
        unsigned short l1 = bfbits(f[2 * j + 1] - bffloat(h1));
        hw[j] = (uint32_t)h0 | ((uint32_t)h1 << 16);
        lw[j] = (uint32_t)l0 | ((uint32_t)l1 << 16);
    }
    #pragma unroll
    for (int cc = 0; cc < 2; cc++) {
        int c = half * 2 + cc;
        uint32_t off = swoff(row, c);
        *(uint4*)(smem + CA_OFF(cbuf) + off) =
            make_uint4(hw[cc * 4], hw[cc * 4 + 1], hw[cc * 4 + 2], hw[cc * 4 + 3]);
        *(uint4*)(smem + CA_OFF(cbuf) + 8192 + off) =
            make_uint4(lw[cc * 4], lw[cc * 4 + 1], lw[cc * 4 + 2], lw[cc * 4 + 3]);
    }
}

__global__ __launch_bounds__(256, 2) void k_mma(const float* __restrict__ X) {
    extern __shared__ __align__(128) char smem[];
    uint32_t sb = smem_u32(smem);
    const int t = threadIdx.x;
    const int warp = t >> 5, lane = t & 31;
    const int by = blockIdx.x;                    // column-variant (fast dim)
    const int m0 = blockIdx.y * 128;              // row block
    const int n0 = by * 128;                      // row into 512-row g_bh/g_bl
    float* __restrict__ O = (by < 2) ? g_xl : g_xr;
    const int col0 = (by & 1) * 128;

    const int wm = (warp & 1) * 64;
    const int wn = (warp >> 1) * 32;

    float acc[4][4][4];
    #pragma unroll
    for (int mi = 0; mi < 4; mi++)
        #pragma unroll
        for (int ni = 0; ni < 4; ni++)
            #pragma unroll
            for (int q = 0; q < 4; q++) acc[mi][ni][q] = 0.f;

    // prologue: stages 0,1 in flight; convert stage 0
    load_rawA_stage(sb, smem, 0, 0, m0, t, X);
    load_B_stage(sb, 0, 0, n0, t);
    asm volatile("cp.async.commit_group;" ::: "memory");
    load_rawA_stage(sb, smem, 1, 1, m0, t, X);
    load_B_stage(sb, 1, 1, n0, t);
    asm volatile("cp.async.commit_group;" ::: "memory");
    asm volatile("cp.async.wait_group 1;" ::: "memory");
    __syncthreads();
    convert_stage(smem, 0, 0, t);
    __syncthreads();

    for (int kt = 0; kt < KT; kt++) {
        // issue stage kt+2 (raw[kt%2] is free: stage kt was converted already)
        if (kt + 2 < KT) {
            load_rawA_stage(sb, smem, kt & 1, kt + 2, m0, t, X);
            load_B_stage(sb, (kt + 2) % 3, kt + 2, n0, t);
            asm volatile("cp.async.commit_group;" ::: "memory");
        }

        // MMA over conv[kt&1] (A) and B[kt%3]
        uint32_t abase = sb + CA_OFF(kt & 1);
        uint32_t bbase = sb + B_OFF(kt % 3);
        #pragma unroll
        for (int kk = 0; kk < 2; kk++) {
            const int kc = kk * 2 + (lane >> 4);
            // pass ordering minimizes live fragments (fit 128 regs for 2 CTAs/SM):
            // 1) ah@bh  2) al@bh (bh dies)  3) ah@bl (ah dies)
            uint32_t ah[4][4], bh[2][4];
            #pragma unroll
            for (int fi = 0; fi < 4; fi++) {
                int row = wm + fi * 16 + (lane & 15);
                ldsm4(abase + swoff(row, kc), ah[fi]);
            }
            #pragma unroll
            for (int nf = 0; nf < 2; nf++) {
                int row = wn + nf * 16 + (lane & 15);
                ldsm4(bbase + swoff(row, kc), bh[nf]);
            }
            #pragma unroll
            for (int mi = 0; mi < 4; mi++)
                #pragma unroll
                for (int ni = 0; ni < 4; ni++) {
                    const int nf = ni >> 1, sel = ni & 1;
                    mma16816(acc[mi][ni], ah[mi], bh[nf][sel], bh[nf][sel + 2]);
                }
            {
                uint32_t al[4][4];
                #pragma unroll
                for (int fi = 0; fi < 4; fi++) {
                    int row = wm + fi * 16 + (lane & 15);
                    ldsm4(abase + 8192 + swoff(row, kc), al[fi]);
                }
                #pragma unroll
                for (int mi = 0; mi < 4; mi++)
                    #pragma unroll
                    for (int ni = 0; ni < 4; ni++) {
                        const int nf = ni >> 1, sel = ni & 1;
                        mma16816(acc[mi][ni], al[mi], bh[nf][sel], bh[nf][sel + 2]);
                    }
            }
            {
                uint32_t bl[2][4];
                #pragma unroll
                for (int nf = 0; nf < 2; nf++) {
                    int row = wn + nf * 16 + (lane & 15);
                    ldsm4(bbase + 8192 + swoff(row, kc), bl[nf]);
                }
                #pragma unroll
                for (int mi = 0; mi < 4; mi++)
                    #pragma unroll
                    for (int ni = 0; ni < 4; ni++) {
                        const int nf = ni >> 1, sel = ni & 1;
                        mma16816(acc[mi][ni], ah[mi], bl[nf][sel], bl[nf][sel + 2]);
                    }
            }
        }

        // prepare stage kt+1: wait its cp.async, then convert raw -> conv[(kt+1)&1]
        if (kt + 1 < KT) {
            if (kt + 2 < KT) asm volatile("cp.async.wait_group 1;" ::: "memory");
            else             asm volatile("cp.async.wait_group 0;" ::: "memory");
            __syncthreads();   // all warps done with MMA kt; raw kt+1 + B kt+1 visible
            convert_stage(smem, (kt + 1) & 1, (kt + 1) & 1, t);
            __syncthreads();   // converted A visible to all warps
        }
    }

    // epilogue: C frag -> fp32 stores (row m = l/4 (+8), col n = (l%4)*2)
    #pragma unroll
    for (int mi = 0; mi < 4; mi++) {
        int mrow0 = m0 + wm + mi * 16 + (lane >> 2);
        #pragma unroll
        for (int half = 0; half < 2; half++) {
            int m = mrow0 + half * 8;
            if (m < NN) {
                float* op = O + (size_t)m * DOUT + col0 + wn + (lane & 3) * 2;
                #pragma unroll
                for (int ni = 0; ni < 4; ni++) {
                    float2 v = make_float2(acc[mi][ni][half * 2], acc[mi][ni][half * 2 + 1]);
                    *(float2*)(op + ni * 8) = v;
                }
            }
        }
    }
}

// ---------------- fused attention softmax + aggregation ----------------
__global__ __launch_bounds__(256) void k_aggregate(
    const float* __restrict__ att,
    const float* __restrict__ bias,
    float* __restrict__ out)
{
    const int gw = (blockIdx.x * blockDim.x + threadIdx.x) >> 5;
    const int lane = threadIdx.x & 31;
    if (gw >= NN) return;

    const int base = lane * 8;
    float4 xr0 = *(const float4*)(g_xr + (size_t)gw * DOUT + base);
    float4 xr1 = *(const float4*)(g_xr + (size_t)gw * DOUT + base + 4);
    float4 at0 = *(const float4*)(att + base);
    float4 at1 = *(const float4*)(att + base + 4);

    float a0 = 0.f, a1 = 0.f, a2 = 0.f, a3 = 0.f;
    float a4 = 0.f, a5 = 0.f, a6 = 0.f, a7 = 0.f;
    float denom = 0.f;

    const int s = g_starts[gw];
    const int cnt = g_counts[gw];

    for (int b = 0; b < cnt; b += 32) {
        int m = cnt - b; if (m > 32) m = 32;
        int sidx = 0;
        if (b + lane < cnt) sidx = g_src_sorted[s + b + lane];

        int src0 = __shfl_sync(0xffffffffu, sidx, 0);
        const float4* xp = (const float4*)(g_xl + (size_t)src0 * DOUT + base);
        float4 v0 = __ldg(xp);
        float4 v1 = __ldg(xp + 1);

        for (int j = 0; j < m; j++) {
            float4 c0 = v0, c1 = v1;
            if (j + 1 < m) {
                int srcn = __shfl_sync(0xffffffffu, sidx, j + 1);
                const float4* xn = (const float4*)(g_xl + (size_t)srcn * DOUT + base);
                v0 = __ldg(xn);
                v1 = __ldg(xn + 1);
            }

            float e = 0.f, z, l;
            z = c0.x + xr0.x; l = fmaxf(z, NEG * z); e = fmaf(l, at0.x, e);
            z = c0.y + xr0.y; l = fmaxf(z, NEG * z); e = fmaf(l, at0.y, e);
            z = c0.z + xr0.z; l = fmaxf(z, NEG * z); e = fmaf(l, at0.z, e);
            z = c0.w + xr0.w; l = fmaxf(z, NEG * z); e = fmaf(l, at0.w, e);
            z = c1.x + xr1.x; l = fmaxf(z, NEG * z); e = fmaf(l, at1.x, e);
            z = c1.y + xr1.y; l = fmaxf(z, NEG * z); e = fmaf(l, at1.y, e);
            z = c1.z + xr1.z; l = fmaxf(z, NEG * z); e = fmaf(l, at1.z, e);
            z = c1.w + xr1.w; l = fmaxf(z, NEG * z); e = fmaf(l, at1.w, e);

            e += __shfl_xor_sync(0xffffffffu, e, 16);
            e += __shfl_xor_sync(0xffffffffu, e, 8);
            e += __shfl_xor_sync(0xffffffffu, e, 4);
            e += __shfl_xor_sync(0xffffffffu, e, 2);
            e += __shfl_xor_sync(0xffffffffu, e, 1);

            float p = __expf(e);
            denom += p;
            a0 = fmaf(p, c0.x, a0); a1 = fmaf(p, c0.y, a1);
            a2 = fmaf(p, c0.z, a2); a3 = fmaf(p, c0.w, a3);
            a4 = fmaf(p, c1.x, a4); a5 = fmaf(p, c1.y, a5);
            a6 = fmaf(p, c1.z, a6); a7 = fmaf(p, c1.w, a7);
        }
    }

    float r = 1.0f / denom;
    float4 b0 = *(const float4*)(bias + base);
    float4 b1 = *(const float4*)(bias + base + 4);
    float4 o0, o1;
    o0.x = fmaf(a0, r, b0.x); o0.y = fmaf(a1, r, b0.y);
    o0.z = fmaf(a2, r, b0.z); o0.w = fmaf(a3, r, b0.w);
    o1.x = fmaf(a4, r, b1.x); o1.y = fmaf(a5, r, b1.y);
    o1.z = fmaf(a6, r, b1.z); o1.w = fmaf(a7, r, b1.w);
    float* op = out + (size_t)gw * DOUT + base;
    *(float4*)(op)     = o0;
    *(float4*)(op + 4) = o1;
}

// ---------------- launch ----------------
extern "C" void kernel_launch(void* const* d_in, const int* in_sizes, int n_in,
                              void* d_out, int out_size) {
    const float* x    = (const float*)d_in[0];
    const void*  ei   = d_in[1];
    const float* Wl   = (const float*)d_in[2];
    const float* Wr   = (const float*)d_in[3];
    const float* att  = (const float*)d_in[4];
    const float* bias = (const float*)d_in[5];
    float*       out  = (float*)d_out;

    cudaFuncSetAttribute(k_mma, cudaFuncAttributeMaxDynamicSharedMemorySize, SMEM_TOT);

    // k_mma kept as my 4th launch (profiled one under -s 5 -c 1 with the
    // ~2 harness-prepended launches)
    k_convB<<<(512 * KP + 255) / 256, 256>>>(Wl, Wr);      // 1
    k_detect<<<1, 32>>>((const int*)ei);                   // 2
    k_zero_counts<<<(NN + 255) / 256, 256>>>();            // 3

    // 4: fused conv + split-bf16 HMMA GEMM (xl / xr), 2 CTAs/SM
    k_mma<<<dim3(4, NNP / 128), 256, SMEM_TOT>>>(x);

    // CSR build (independent of GEMM)
    k_hist<<<(TOT + 255) / 256, 256>>>(ei);                // 5
    k_scan1<<<NBS, 512>>>();                               // 6
    k_scan2<<<1, 32>>>();                                  // 7
    k_scan3<<<(NN + 255) / 256, 256>>>();                  // 8
    k_scatter<<<(TOT + 255) / 256, 256>>>(ei);             // 9

    // fused softmax + aggregation
    k_aggregate<<<(NN * 32) / 256, 256>>>(att, bias, out); // 10
}

// round 17
// speedup vs baseline: 1.5337x; 1.0097x over previous
#include <cuda_runtime.h>
#include <cuda_bf16.h>
#include <cstdint>

#define NN 50000          // nodes
#define NNP 50048         // padded to 128-multiple
#define NE 1600000        // edges
#define TOT (NE + NN)     // edges + self loops
#define KDIM 1028
#define KP 1056           // K padded (33 * 32)
#define DOUT 256
#define NEG 0.2f
#define NBS ((NN + 511) / 512)

#define BK 32
#define KT (KP / BK)              // 33 k-tiles
// smem layout (per CTA, 112 KB -> 2 CTAs/SM on 228KB):
//   B stages:   3 x 16 KB  (Bh 8K + Bl 8K, swizzled)      @ 0
//   rawA:       2 x 16 KB  (128 rows x 32 fp32, linear)    @ 48K
//   convA:      2 x 16 KB  (Ah 8K + Al 8K, swizzled)       @ 80K
#define B_OFF(buf)   ((buf) * 16384)
#define RAW_OFF(buf) (49152 + (buf) * 16384)
#define CA_OFF(buf)  (81920 + (buf) * 16384)
#define SMEM_TOT 114688

// ---------------- scratch (static device globals; no allocation) ----------------
__device__ float g_xl[(size_t)NNP * DOUT];
__device__ float g_xr[(size_t)NNP * DOUT];
__device__ unsigned short g_bh[512 * KP];   // W^T hi ([n][k]; n<256: Wl, else Wr)
__device__ unsigned short g_bl[512 * KP];   // W^T lo
__device__ int   g_counts[NN];
__device__ int   g_starts[NN];
__device__ int   g_work[NN];
__device__ int   g_src_sorted[TOT];
__device__ int   g_bsum[NBS];
__device__ int   g_is64;

// ---------------- small helpers ----------------
__device__ __forceinline__ unsigned short bfbits(float f) {
    __nv_bfloat16 h = __float2bfloat16(f);
    return *reinterpret_cast<unsigned short*>(&h);
}
__device__ __forceinline__ float bffloat(unsigned short u) {
    __nv_bfloat16 h = *reinterpret_cast<__nv_bfloat16*>(&u);
    return __bfloat162float(h);
}
__device__ __forceinline__ uint32_t smem_u32(const void* p) {
    uint32_t a;
    asm("{ .reg .u64 t; cvta.to.shared.u64 t, %1; cvt.u32.u64 %0, t; }" : "=r"(a) : "l"(p));
    return a;
}
__device__ __forceinline__ void cpa16(uint32_t s, const void* g) {
    asm volatile("cp.async.cg.shared.global [%0], [%1], 16;" :: "r"(s), "l"(g));
}
__device__ __forceinline__ void ldsm4(uint32_t addr, uint32_t* r) {
    asm volatile("ldmatrix.sync.aligned.m8n8.x4.shared.b16 {%0,%1,%2,%3}, [%4];"
                 : "=r"(r[0]), "=r"(r[1]), "=r"(r[2]), "=r"(r[3]) : "r"(addr));
}
__device__ __forceinline__ void mma16816(float* d, const uint32_t* a, uint32_t b0, uint32_t b1) {
    asm volatile(
        "mma.sync.aligned.m16n8k16.row.col.f32.bf16.bf16.f32 "
        "{%0,%1,%2,%3}, {%4,%5,%6,%7}, {%8,%9}, {%0,%1,%2,%3};"
        : "+f"(d[0]), "+f"(d[1]), "+f"(d[2]), "+f"(d[3])
        : "r"(a[0]), "r"(a[1]), "r"(a[2]), "r"(a[3]), "r"(b0), "r"(b1));
}
// 16B-chunk XOR swizzle inside a 128x32 bf16 tile: row stride 64B, 4 chunks/row
__device__ __forceinline__ uint32_t swoff(int row, int kchunk) {
    return (uint32_t)row * 64 + ((kchunk ^ ((row >> 1) & 3)) * 16);
}

// ---------------- convB: fp32 W -> split bf16 W^T (hi/lo), padded ----------------
__global__ void k_convB(const float* __restrict__ Wl, const float* __restrict__ Wr) {
    int idx = blockIdx.x * blockDim.x + threadIdx.x;
    if (idx >= 512 * KP) return;
    int n = idx / KP, k = idx % KP;
    float v = 0.f;
    if (k < KDIM) v = (n < 256) ? Wl[(size_t)k * 256 + n] : Wr[(size_t)k * 256 + (n - 256)];
    unsigned short h = bfbits(v);
    unsigned short l = bfbits(v - bffloat(h));
    g_bh[idx] = h;
    g_bl[idx] = l;
}

// ---------------- CSR init + edge dtype detection (fused) ----------------
// JAX may downcast int64->int32; detect actual layout: int64 LE => every odd
// 32-bit word of the first 64 entries is 0 (values < 50000).
__global__ void k_init(const int* __restrict__ e32) {
    int i = blockIdx.x * blockDim.x + threadIdx.x;
    if (i < NN) g_counts[i] = 0;
    if (i == 0) {
        int is64 = 1;
        for (int q = 0; q < 64; q++)
            if (e32[2 * q + 1] != 0) { is64 = 0; break; }
        g_is64 = is64;
    }
}
__device__ __forceinline__ int edge_at(const void* ei, int idx) {
    if (g_is64) return (int)((const long long*)ei)[idx];
    return ((const int*)ei)[idx];
}

// ---------------- CSR build ----------------
__global__ void k_hist(const void* __restrict__ ei) {
    int k = blockIdx.x * blockDim.x + threadIdx.x;
    if (k >= TOT) return;
    int dst = (k < NE) ? edge_at(ei, NE + k) : (k - NE);
    if ((unsigned)dst < NN) atomicAdd(&g_counts[dst], 1);
}
__global__ void k_scan1() {
    __shared__ int sh[512];
    int t = threadIdx.x;
    int i = blockIdx.x * 512 + t;
    int v = (i < NN) ? g_counts[i] : 0;
    sh[t] = v;
    __syncthreads();
    #pragma unroll
    for (int o = 1; o < 512; o <<= 1) {
        int u = (t >= o) ? sh[t - o] : 0;
        __syncthreads();
        sh[t] += u;
        __syncthreads();
    }
    if (i < NN) g_starts[i] = sh[t] - v;
    if (t == 511) g_bsum[blockIdx.x] = sh[t];
}
__global__ void k_scan2() {
    if (threadIdx.x == 0 && blockIdx.x == 0) {
        int run = 0;
        for (int b = 0; b < NBS; b++) { int c = g_bsum[b]; g_bsum[b] = run; run += c; }
    }
}
__global__ void k_scan3() {
    int i = blockIdx.x * blockDim.x + threadIdx.x;
    if (i >= NN) return;
    int s = g_starts[i] + g_bsum[i >> 9];
    g_starts[i] = s;
    g_work[i] = s;
}
__global__ void k_scatter(const void* __restrict__ ei) {
    int k = blockIdx.x * blockDim.x + threadIdx.x;
    if (k >= TOT) return;
    int src, dst;
    if (k < NE) { src = edge_at(ei, k); dst = edge_at(ei, NE + k); }
    else        { src = k - NE;         dst = k - NE; }
    if ((unsigned)dst >= NN || (unsigned)src >= NN) return;
    int pos = atomicAdd(&g_work[dst], 1);
    g_src_sorted[pos] = src;
}

// ---------------- fused conv + split-bf16 HMMA GEMM ----------------
// D = Ah@Bh^T + Ah@Bl^T + Al@Bh^T, fp32 accum shared across the 3 passes.
// A loaded as RAW fp32 X, TRUNCATION-split to bf16 hi/lo in-kernel via PRMT
// (hi = top 16 bits; lo = f - hi, exact fp32 sub; no cvt instructions).
// CTA: BM=128 x BN=128, BK=32, 8 warps, warp tile 64x32, 2 CTAs/SM.
// grid = (4, NNP/128): bx fast -> X tile L2-reused across the 4 col-variants.
__device__ __forceinline__ void load_B_stage(uint32_t sb, int buf, int kt, int n0, int t) {
    int k0 = kt * BK;
    #pragma unroll
    for (int p = 0; p < 4; p++) {
        int id = p * 256 + t;
        int mat = id >> 9;            // 0 Bh, 1 Bl
        int cid = id & 511;
        int row = cid >> 2;
        int c = cid & 3;
        uint32_t dst = sb + B_OFF(buf) + mat * 8192 + swoff(row, c);
        const unsigned short* src = (mat ? g_bl : g_bh) + (size_t)(n0 + row) * KP + k0 + c * 8;
        cpa16(dst, src);
    }
}

__device__ __forceinline__ void load_rawA_stage(uint32_t sb, char* smem, int buf, int kt,
                                                int m0, int t, const float* __restrict__ X) {
    int k0 = kt * BK;
    #pragma unroll
    for (int p = 0; p < 4; p++) {
        int id = p * 256 + t;
        int row = id >> 3;            // 0..127
        int c = id & 7;               // 8 chunks of 4 floats per row
        int col = k0 + c * 4;
        uint32_t dsto = RAW_OFF(buf) + (uint32_t)row * 128 + c * 16;
        int m = m0 + row;
        if (m < NN && col + 4 <= KDIM) {
            cpa16(sb + dsto, X + (size_t)m * KDIM + col);
        } else {
            *(float4*)(smem + dsto) = make_float4(0.f, 0.f, 0.f, 0.f);
        }
    }
}

// truncation split: hi = top16(f) (PRMT-packed), lo = f - hi (exact), PRMT-packed
__device__ __forceinline__ void convert_stage(char* smem, int rawbuf, int cbuf, int t) {
    const int row = t >> 1;
    const int half = t & 1;            // cols [half*16, half*16+16)
    const float4* rp = (const float4*)(smem + RAW_OFF(rawbuf) + (uint32_t)row * 128 + half * 64);
    float f[16];
    #pragma unroll
    for (int q = 0; q < 4; q++) {
        float4 v = rp[q];
        f[q * 4 + 0] = v.x; f[q * 4 + 1] = v.y; f[q * 4 + 2] = v.z; f[q * 4 + 3] = v.w;
    }
    uint32_t hw[8], lw[8];
    #pragma unroll
    for (int j = 0; j < 8; j++) {
        uint32_t a = __float_as_uint(f[2 * j]);
        uint32_t b = __float_as_uint(f[2 * j + 1]);
        hw[j] = __byte_perm(a, b, 0x7632);                 // [hi16(f0) | hi16(f1)<<16]
        float h0 = __uint_as_float(a & 0xFFFF0000u);
        float h1 = __uint_as_float(b & 0xFFFF0000u);
        float l0 = f[2 * j]     - h0;
        float l1 = f[2 * j + 1] - h1;
        lw[j] = __byte_perm(__float_as_uint(l0), __float_as_uint(l1), 0x7632);
    }
    #pragma unroll
    for (int cc = 0; cc < 2; cc++) {
        int c = half * 2 + cc;
        uint32_t off = swoff(row, c);
        *(uint4*)(smem + CA_OFF(cbuf) + off) =
            make_uint4(hw[cc * 4], hw[cc * 4 + 1], hw[cc * 4 + 2], hw[cc * 4 + 3]);
        *(uint4*)(smem + CA_OFF(cbuf) + 8192 + off) =
            make_uint4(lw[cc * 4], lw[cc * 4 + 1], lw[cc * 4 + 2], lw[cc * 4 + 3]);
    }
}

__global__ __launch_bounds__(256, 2) void k_mma(const float* __restrict__ X) {
    extern __shared__ __align__(128) char smem[];
    uint32_t sb = smem_u32(smem);
    const int t = threadIdx.x;
    const int warp = t >> 5, lane = t & 31;
    const int by = blockIdx.x;                    // column-variant (fast dim)
    const int m0 = blockIdx.y * 128;              // row block
    const int n0 = by * 128;                      // row into 512-row g_bh/g_bl
    float* __restrict__ O = (by < 2) ? g_xl : g_xr;
    const int col0 = (by & 1) * 128;

    const int wm = (warp & 1) * 64;
    const int wn = (warp >> 1) * 32;

    float acc[4][4][4];
    #pragma unroll
    for (int mi = 0; mi < 4; mi++)
        #pragma unroll
        for (int ni = 0; ni < 4; ni++)
            #pragma unroll
            for (int q = 0; q < 4; q++) acc[mi][ni][q] = 0.f;

    // prologue: stages 0,1 in flight; convert stage 0
    load_rawA_stage(sb, smem, 0, 0, m0, t, X);
    load_B_stage(sb, 0, 0, n0, t);
    asm volatile("cp.async.commit_group;" ::: "memory");
    load_rawA_stage(sb, smem, 1, 1, m0, t, X);
    load_B_stage(sb, 1, 1, n0, t);
    asm volatile("cp.async.commit_group;" ::: "memory");
    asm volatile("cp.async.wait_group 1;" ::: "memory");
    __syncthreads();
    convert_stage(smem, 0, 0, t);
    __syncthreads();

    for (int kt = 0; kt < KT; kt++) {
        // issue stage kt+2 (raw[kt%2] is free: stage kt was converted already)
        if (kt + 2 < KT) {
            load_rawA_stage(sb, smem, kt & 1, kt + 2, m0, t, X);
            load_B_stage(sb, (kt + 2) % 3, kt + 2, n0, t);
            asm volatile("cp.async.commit_group;" ::: "memory");
        }

        // MMA over conv[kt&1] (A) and B[kt%3]
        uint32_t abase = sb + CA_OFF(kt & 1);
        uint32_t bbase = sb + B_OFF(kt % 3);
        #pragma unroll
        for (int kk = 0; kk < 2; kk++) {
            const int kc = kk * 2 + (lane >> 4);
            // pass ordering minimizes live fragments (fit 128 regs for 2 CTAs/SM):
            // 1) ah@bh  2) al@bh  3) ah@bl
            uint32_t ah[4][4], bh[2][4];
            #pragma unroll
            for (int fi = 0; fi < 4; fi++) {
                int row = wm + fi * 16 + (lane & 15);
                ldsm4(abase + swoff(row, kc), ah[fi]);
            }
            #pragma unroll
            for (int nf = 0; nf < 2; nf++) {
                int row = wn + nf * 16 + (lane & 15);
                ldsm4(bbase + swoff(row, kc), bh[nf]);
            }
            #pragma unroll
            for (int mi = 0; mi < 4; mi++)
                #pragma unroll
                for (int ni = 0; ni < 4; ni++) {
                    const int nf = ni >> 1, sel = ni & 1;
                    mma16816(acc[mi][ni], ah[mi], bh[nf][sel], bh[nf][sel + 2]);
                }
            {
                uint32_t al[4][4];
                #pragma unroll
                for (int fi = 0; fi < 4; fi++) {
                    int row = wm + fi * 16 + (lane & 15);
                    ldsm4(abase + 8192 + swoff(row, kc), al[fi]);
                }
                #pragma unroll
                for (int mi = 0; mi < 4; mi++)
                    #pragma unroll
                    for (int ni = 0; ni < 4; ni++) {
                        const int nf = ni >> 1, sel = ni & 1;
                        mma16816(acc[mi][ni], al[mi], bh[nf][sel], bh[nf][sel + 2]);
                    }
            }
            {
                uint32_t bl[2][4];
                #pragma unroll
                for (int nf = 0; nf < 2; nf++) {
                    int row = wn + nf * 16 + (lane & 15);
                    ldsm4(bbase + 8192 + swoff(row, kc), bl[nf]);
                }
                #pragma unroll
                for (int mi = 0; mi < 4; mi++)
                    #pragma unroll
                    for (int ni = 0; ni < 4; ni++) {
                        const int nf = ni >> 1, sel = ni & 1;
                        mma16816(acc[mi][ni], ah[mi], bl[nf][sel], bl[nf][sel + 2]);
                    }
            }
        }

        // prepare stage kt+1: wait its cp.async, then convert raw -> conv[(kt+1)&1]
        if (kt + 1 < KT) {
            if (kt + 2 < KT) asm volatile("cp.async.wait_group 1;" ::: "memory");
            else             asm volatile("cp.async.wait_group 0;" ::: "memory");
            __syncthreads();   // all warps done with MMA kt; raw kt+1 + B kt+1 visible
            convert_stage(smem, (kt + 1) & 1, (kt + 1) & 1, t);
            __syncthreads();   // converted A visible to all warps
        }
    }

    // epilogue: C frag -> fp32 stores (row m = l/4 (+8), col n = (l%4)*2)
    #pragma unroll
    for (int mi = 0; mi < 4; mi++) {
        int mrow0 = m0 + wm + mi * 16 + (lane >> 2);
        #pragma unroll
        for (int half = 0; half < 2; half++) {
            int m = mrow0 + half * 8;
            if (m < NN) {
                float* op = O + (size_t)m * DOUT + col0 + wn + (lane & 3) * 2;
                #pragma unroll
                for (int ni = 0; ni < 4; ni++) {
                    float2 v = make_float2(acc[mi][ni][half * 2], acc[mi][ni][half * 2 + 1]);
                    *(float2*)(op + ni * 8) = v;
                }
            }
        }
    }
}

// ---------------- fused attention softmax + aggregation ----------------
__global__ __launch_bounds__(256) void k_aggregate(
    const float* __restrict__ att,
    const float* __restrict__ bias,
    float* __restrict__ out)
{
    const int gw = (blockIdx.x * blockDim.x + threadIdx.x) >> 5;
    const int lane = threadIdx.x & 31;
    if (gw >= NN) return;

    const int base = lane * 8;
    float4 xr0 = *(const float4*)(g_xr + (size_t)gw * DOUT + base);
    float4 xr1 = *(const float4*)(g_xr + (size_t)gw * DOUT + base + 4);
    float4 at0 = *(const float4*)(att + base);
    float4 at1 = *(const float4*)(att + base + 4);

    float a0 = 0.f, a1 = 0.f, a2 = 0.f, a3 = 0.f;
    float a4 = 0.f, a5 = 0.f, a6 = 0.f, a7 = 0.f;
    float denom = 0.f;

    const int s = g_starts[gw];
    const int cnt = g_counts[gw];

    for (int b = 0; b < cnt; b += 32) {
        int m = cnt - b; if (m > 32) m = 32;
        int sidx = 0;
        if (b + lane < cnt) sidx = g_src_sorted[s + b + lane];

        int src0 = __shfl_sync(0xffffffffu, sidx, 0);
        const float4* xp = (const float4*)(g_xl + (size_t)src0 * DOUT + base);
        float4 v0 = __ldg(xp);
        float4 v1 = __ldg(xp + 1);

        for (int j = 0; j < m; j++) {
            float4 c0 = v0, c1 = v1;
            if (j + 1 < m) {
                int srcn = __shfl_sync(0xffffffffu, sidx, j + 1);
                const float4* xn = (const float4*)(g_xl + (size_t)srcn * DOUT + base);
                v0 = __ldg(xn);
                v1 = __ldg(xn + 1);
            }

            float e = 0.f, z, l;
            z = c0.x + xr0.x; l = fmaxf(z, NEG * z); e = fmaf(l, at0.x, e);
            z = c0.y + xr0.y; l = fmaxf(z, NEG * z); e = fmaf(l, at0.y, e);
            z = c0.z + xr0.z; l = fmaxf(z, NEG * z); e = fmaf(l, at0.z, e);
            z = c0.w + xr0.w; l = fmaxf(z, NEG * z); e = fmaf(l, at0.w, e);
            z = c1.x + xr1.x; l = fmaxf(z, NEG * z); e = fmaf(l, at1.x, e);
            z = c1.y + xr1.y; l = fmaxf(z, NEG * z); e = fmaf(l, at1.y, e);
            z = c1.z + xr1.z; l = fmaxf(z, NEG * z); e = fmaf(l, at1.z, e);
            z = c1.w + xr1.w; l = fmaxf(z, NEG * z); e = fmaf(l, at1.w, e);

            e += __shfl_xor_sync(0xffffffffu, e, 16);
            e += __shfl_xor_sync(0xffffffffu, e, 8);
            e += __shfl_xor_sync(0xffffffffu, e, 4);
            e += __shfl_xor_sync(0xffffffffu, e, 2);
            e += __shfl_xor_sync(0xffffffffu, e, 1);

            float p = __expf(e);
            denom += p;
            a0 = fmaf(p, c0.x, a0); a1 = fmaf(p, c0.y, a1);
            a2 = fmaf(p, c0.z, a2); a3 = fmaf(p, c0.w, a3);
            a4 = fmaf(p, c1.x, a4); a5 = fmaf(p, c1.y, a5);
            a6 = fmaf(p, c1.z, a6); a7 = fmaf(p, c1.w, a7);
        }
    }

    float r = 1.0f / denom;
    float4 b0 = *(const float4*)(bias + base);
    float4 b1 = *(const float4*)(bias + base + 4);
    float4 o0, o1;
    o0.x = fmaf(a0, r, b0.x); o0.y = fmaf(a1, r, b0.y);
    o0.z = fmaf(a2, r, b0.z); o0.w = fmaf(a3, r, b0.w);
    o1.x = fmaf(a4, r, b1.x); o1.y = fmaf(a5, r, b1.y);
    o1.z = fmaf(a6, r, b1.z); o1.w = fmaf(a7, r, b1.w);
    float* op = out + (size_t)gw * DOUT + base;
    *(float4*)(op)     = o0;
    *(float4*)(op + 4) = o1;
}

// ---------------- launch ----------------
extern "C" void kernel_launch(void* const* d_in, const int* in_sizes, int n_in,
                              void* d_out, int out_size) {
    const float* x    = (const float*)d_in[0];
    const void*  ei   = d_in[1];
    const float* Wl   = (const float*)d_in[2];
    const float* Wr   = (const float*)d_in[3];
    const float* att  = (const float*)d_in[4];
    const float* bias = (const float*)d_in[5];
    float*       out  = (float*)d_out;

    cudaFuncSetAttribute(k_mma, cudaFuncAttributeMaxDynamicSharedMemorySize, SMEM_TOT);

    k_convB<<<(512 * KP + 255) / 256, 256>>>(Wl, Wr);      // 1
    k_init<<<(NN + 255) / 256, 256>>>((const int*)ei);     // 2 (zero counts + dtype detect)
    k_hist<<<(TOT + 255) / 256, 256>>>(ei);                // 3

    // 4: fused trunc-split bf16 HMMA GEMM (xl / xr), 2 CTAs/SM
    k_mma<<<dim3(4, NNP / 128), 256, SMEM_TOT>>>(x);

    // CSR back half (independent of GEMM)
    k_scan1<<<NBS, 512>>>();                               // 5
    k_scan2<<<1, 32>>>();                                  // 6
    k_scan3<<<(NN + 255) / 256, 256>>>();                  // 7
    k_scatter<<<(TOT + 255) / 256, 256>>>(ei);             // 8

    // fused softmax + aggregation
    k_aggregate<<<(NN * 32) / 256, 256>>>(att, bias, out); // 9
}